// round 10
// baseline (speedup 1.0000x reference)
#include <cuda_runtime.h>

// Problem constants (fixed shapes)
#define NN 100000
#define EE 1600000
#define CC 128
#define BN_EPS 1e-5f

// ---------------- scratch (device globals: no allocation allowed) ----------
__device__ int   g_is64;                 // edge_index dtype flag (1 = int64)
__device__ int   g_count[NN];
__device__ int   g_offsets[NN + 1];
__device__ int   g_cursor[NN];
__device__ int   g_csr[EE];
__device__ float g_dinv[NN];
__device__ float g_H[(size_t)NN * CC];   // 51.2 MB
__device__ float g_A[(size_t)NN * CC];   // 51.2 MB
__device__ int   g_bsum[128];            // scan block partials (98 used)
__device__ float g_sum[CC];
__device__ float g_sumsq[CC];
__device__ float g_scale[CC];
__device__ float g_shift[CC];

// ---------------- edge dtype detection --------------------------------------
// int64 node ids (< 2^31, non-negative) have all-zero high 32-bit words.
// int32 edge data has random ids in [0, 100000) at those word positions.
__global__ void k_detect(const unsigned int* __restrict__ w) {
    int nz = 0;
    for (int i = threadIdx.x; i < 512; i += 32)
        if (w[2 * i + 1] != 0u) nz++;
#pragma unroll
    for (int o = 16; o; o >>= 1) nz += __shfl_xor_sync(0xffffffffu, nz, o);
    if (threadIdx.x == 0) g_is64 = (nz == 0) ? 1 : 0;
}

__device__ __forceinline__ int edge_at(const void* eiv, int idx) {
    if (g_is64) return (int)((const long long*)eiv)[idx];
    return ((const int*)eiv)[idx];
}

// ---------------- CSR build --------------------------------------------------
__global__ void k_zero_count() {
    int i = blockIdx.x * blockDim.x + threadIdx.x;
    if (i < NN) g_count[i] = 0;
}

__global__ void k_hist(const void* __restrict__ eiv) {
    int e = blockIdx.x * blockDim.x + threadIdx.x;
    if (e < EE) atomicAdd(&g_count[edge_at(eiv, EE + e)], 1);
}

// 98 blocks x 256 threads, segment = 1024 counts per block
__global__ void k_scan_partial() {
    __shared__ int s[256];
    int b = blockIdx.x, t = threadIdx.x;
    int sum = 0;
    for (int i = t; i < 1024; i += 256) {
        int idx = b * 1024 + i;
        if (idx < NN) sum += g_count[idx];
    }
    s[t] = sum;
    __syncthreads();
    for (int off = 128; off > 0; off >>= 1) {
        if (t < off) s[t] += s[t + off];
        __syncthreads();
    }
    if (t == 0) g_bsum[b] = s[0];
}

__global__ void k_scan_boff() {   // 1 block, 128 threads
    __shared__ int s[128];
    int t = threadIdx.x;
    s[t] = (t < 98) ? g_bsum[t] : 0;
    __syncthreads();
    if (t == 0) {
        int run = 0;
        for (int i = 0; i < 98; i++) { int v = s[i]; s[i] = run; run += v; }
    }
    __syncthreads();
    if (t < 98) g_bsum[t] = s[t];
}

// 98 blocks x 256 threads: write exclusive offsets, cursor, dinv
__global__ void k_scan_write() {
    __shared__ int s[256];
    int b = blockIdx.x, t = threadIdx.x;
    int run = g_bsum[b];
    for (int tile = 0; tile < 4; tile++) {
        int idx = b * 1024 + tile * 256 + t;
        int v = (idx < NN) ? g_count[idx] : 0;
        s[t] = v;
        __syncthreads();
        for (int off = 1; off < 256; off <<= 1) {
            int add = (t >= off) ? s[t - off] : 0;
            __syncthreads();
            s[t] += add;
            __syncthreads();
        }
        int excl = s[t] - v;
        if (idx <= NN) g_offsets[idx] = run + excl;
        if (idx < NN) {
            g_cursor[idx] = run + excl;
            g_dinv[idx]   = rsqrtf((float)v + 1.0f);
        }
        int tot = s[255];
        __syncthreads();
        run += tot;
    }
}

__global__ void k_fill(const void* __restrict__ eiv) {
    int e = blockIdx.x * blockDim.x + threadIdx.x;
    if (e < EE) {
        int dst = edge_at(eiv, EE + e);
        int src = edge_at(eiv, e);
        int pos = atomicAdd(&g_cursor[dst], 1);
        g_csr[pos] = src;
    }
}

// ---------------- GEMM: C[NN,128] = A[NN,128] x W[128,128] (fp32) -----------
// 256 threads, tile 64 rows x 128 cols. Thread (tx=tid&31, ty=tid>>5) computes
// an 8x4 micro-tile: rows ty*8..+7, cols tx*4..+3 (float4 everywhere).
__global__ __launch_bounds__(256) void k_gemm(const float* __restrict__ A,
                                              const float* __restrict__ W,
                                              float* __restrict__ Cout) {
    __shared__ float sA[64][36];     // 32 K-cols, padded (keeps float4 align)
    __shared__ float sB[32][128];
    int tid = threadIdx.x;
    int tx = tid & 31;          // column group: cols tx*4..tx*4+3
    int ty = tid >> 5;          // row group:    rows ty*8..ty*8+7
    int row0 = blockIdx.x * 64;

    float4 acc[8];
#pragma unroll
    for (int i = 0; i < 8; i++) acc[i] = make_float4(0.f, 0.f, 0.f, 0.f);

    for (int kc = 0; kc < CC; kc += 32) {
        // load A tile 64x32 as float4 (512 float4, 2 per thread)
#pragma unroll
        for (int u = 0; u < 2; u++) {
            int f = tid * 2 + u;          // 0..511
            int m = f >> 3;               // row in tile
            int k = (f & 7) * 4;          // col in k-tile
            int r = row0 + m;
            float4 v = make_float4(0.f, 0.f, 0.f, 0.f);
            if (r < NN) v = *(const float4*)(A + (size_t)r * CC + kc + k);
            *(float4*)(&sA[m][k]) = v;
        }
        // load W tile 32x128 as float4 (1024 float4, 4 per thread)
#pragma unroll
        for (int u = 0; u < 4; u++) {
            int f = tid + u * 256;        // 0..1023
            int k = f >> 5;
            int n = (f & 31) * 4;
            *(float4*)(&sB[k][n]) = *(const float4*)(W + (size_t)(kc + k) * CC + n);
        }
        __syncthreads();
#pragma unroll
        for (int k = 0; k < 32; k++) {
            float4 bv = *(const float4*)(&sB[k][tx * 4]);
#pragma unroll
            for (int i = 0; i < 8; i++) {
                float a = sA[ty * 8 + i][k];     // broadcast within warp
                acc[i].x += a * bv.x;
                acc[i].y += a * bv.y;
                acc[i].z += a * bv.z;
                acc[i].w += a * bv.w;
            }
        }
        __syncthreads();
    }
#pragma unroll
    for (int i = 0; i < 8; i++) {
        int r = row0 + ty * 8 + i;
        if (r < NN)
            *(float4*)(Cout + (size_t)r * CC + tx * 4) = acc[i];
    }
}

// ---------------- aggregation: one warp per dst node -------------------------
__global__ __launch_bounds__(256) void k_aggregate(const float* __restrict__ Hin,
                                                   const float* __restrict__ bias,
                                                   float* __restrict__ Aout) {
    int gw = (blockIdx.x * blockDim.x + threadIdx.x) >> 5;
    int lane = threadIdx.x & 31;
    if (gw >= NN) return;
    int i = gw;
    int beg = g_offsets[i], end = g_offsets[i + 1];
    float4 acc0 = make_float4(0.f, 0.f, 0.f, 0.f);
    float4 acc1 = make_float4(0.f, 0.f, 0.f, 0.f);
    int e = beg;
    // 2-way unrolled to expose memory-level parallelism
    for (; e + 1 < end; e += 2) {
        int s0 = g_csr[e];
        int s1 = g_csr[e + 1];
        float w0 = g_dinv[s0];
        float w1 = g_dinv[s1];
        float4 h0 = *(const float4*)(Hin + (size_t)s0 * CC + lane * 4);
        float4 h1 = *(const float4*)(Hin + (size_t)s1 * CC + lane * 4);
        acc0.x += h0.x * w0; acc0.y += h0.y * w0;
        acc0.z += h0.z * w0; acc0.w += h0.w * w0;
        acc1.x += h1.x * w1; acc1.y += h1.y * w1;
        acc1.z += h1.z * w1; acc1.w += h1.w * w1;
    }
    if (e < end) {
        int s0 = g_csr[e];
        float w0 = g_dinv[s0];
        float4 h0 = *(const float4*)(Hin + (size_t)s0 * CC + lane * 4);
        acc0.x += h0.x * w0; acc0.y += h0.y * w0;
        acc0.z += h0.z * w0; acc0.w += h0.w * w0;
    }
    acc0.x += acc1.x; acc0.y += acc1.y; acc0.z += acc1.z; acc0.w += acc1.w;

    float di = g_dinv[i];
    float dii = di * di;
    float4 hs = *(const float4*)(Hin + (size_t)i * CC + lane * 4);
    float4 bb = *(const float4*)(bias + lane * 4);
    float4 o;
    o.x = acc0.x * di + hs.x * dii + bb.x;
    o.y = acc0.y * di + hs.y * dii + bb.y;
    o.z = acc0.z * di + hs.z * dii + bb.z;
    o.w = acc0.w * di + hs.w * dii + bb.w;
    *(float4*)(Aout + (size_t)i * CC + lane * 4) = o;
}

// ---------------- BatchNorm --------------------------------------------------
__global__ void k_zero_stats() {
    int c = threadIdx.x;
    g_sum[c] = 0.f;
    g_sumsq[c] = 0.f;
}

// block = 128 threads (one per channel), 256 rows per block
__global__ __launch_bounds__(128) void k_stats(const float* __restrict__ X) {
    int c = threadIdx.x;
    int r0 = blockIdx.x * 256;
    float s = 0.f, sq = 0.f;
#pragma unroll 4
    for (int r = 0; r < 256; r++) {
        int row = r0 + r;
        if (row < NN) {
            float v = X[(size_t)row * CC + c];
            s += v;
            sq += v * v;
        }
    }
    atomicAdd(&g_sum[c], s);
    atomicAdd(&g_sumsq[c], sq);
}

__global__ void k_params(const float* __restrict__ gamma,
                         const float* __restrict__ beta) {
    int c = threadIdx.x;
    float inv_n = 1.0f / (float)NN;
    float mean = g_sum[c] * inv_n;
    float var = g_sumsq[c] * inv_n - mean * mean;
    float istd = rsqrtf(var + BN_EPS);
    float sc = istd * gamma[c];
    g_scale[c] = sc;
    g_shift[c] = beta[c] - mean * sc;
}

// relu(bn(x)) elementwise, float4-vectorized
__global__ __launch_bounds__(256) void k_bnrelu(const float* __restrict__ X,
                                                float* __restrict__ Y) {
    int idx = blockIdx.x * blockDim.x + threadIdx.x;
    if (idx >= NN * 32) return;
    int c = (idx & 31) * 4;
    float4 sc = *(const float4*)(&g_scale[c]);
    float4 sh = *(const float4*)(&g_shift[c]);
    float4 v = ((const float4*)X)[idx];
    v.x = fmaxf(v.x * sc.x + sh.x, 0.f);
    v.y = fmaxf(v.y * sc.y + sh.y, 0.f);
    v.z = fmaxf(v.z * sc.z + sh.z, 0.f);
    v.w = fmaxf(v.w * sc.w + sh.w, 0.f);
    ((float4*)Y)[idx] = v;
}

// relu(bn(z) + x) elementwise (final), in-place on d_out
__global__ __launch_bounds__(256) void k_final(const float* __restrict__ Z,
                                               const float* __restrict__ Xres,
                                               float* __restrict__ Out) {
    int idx = blockIdx.x * blockDim.x + threadIdx.x;
    if (idx >= NN * 32) return;
    int c = (idx & 31) * 4;
    float4 sc = *(const float4*)(&g_scale[c]);
    float4 sh = *(const float4*)(&g_shift[c]);
    float4 v = ((const float4*)Z)[idx];
    float4 xv = ((const float4*)Xres)[idx];
    v.x = fmaxf(v.x * sc.x + sh.x + xv.x, 0.f);
    v.y = fmaxf(v.y * sc.y + sh.y + xv.y, 0.f);
    v.z = fmaxf(v.z * sc.z + sh.z + xv.z, 0.f);
    v.w = fmaxf(v.w * sc.w + sh.w + xv.w, 0.f);
    ((float4*)Out)[idx] = v;
}

// ---------------- launch -----------------------------------------------------
extern "C" void kernel_launch(void* const* d_in, const int* in_sizes, int n_in,
                              void* d_out, int out_size) {
    (void)in_sizes; (void)n_in; (void)out_size;
    const float* x      = (const float*)d_in[0];
    const float* W1     = (const float*)d_in[1];
    const float* b1     = (const float*)d_in[2];
    const float* W2     = (const float*)d_in[3];
    const float* b2     = (const float*)d_in[4];
    const float* gamma2 = (const float*)d_in[5];
    const float* beta2  = (const float*)d_in[6];
    const void*  ei     = d_in[7];
    float* out = (float*)d_out;

    float* H = nullptr;
    float* A = nullptr;
    cudaGetSymbolAddress((void**)&H, g_H);
    cudaGetSymbolAddress((void**)&A, g_A);

    const int TB = 256;
    const int gN    = (NN + TB - 1) / TB;            // 391
    const int gE    = (EE + TB - 1) / TB;            // 6250
    const int gGemm = (NN + 63) / 64;                // 1563
    const int gAgg  = (NN * 32 + TB - 1) / TB;       // 12500 (8 warps/block)
    const int gVec  = (NN * 32 + TB - 1) / TB;       // 12500
    const int gStat = (NN + 255) / 256;              // 391

    // edge dtype detect + CSR build (once per launch; used by both convs)
    k_detect<<<1, 32>>>((const unsigned int*)ei);
    k_zero_count<<<gN, TB>>>();
    k_hist<<<gE, TB>>>(ei);
    k_scan_partial<<<98, 256>>>();
    k_scan_boff<<<1, 128>>>();
    k_scan_write<<<98, 256>>>();
    k_fill<<<gE, TB>>>(ei);

    // conv1: H = x @ W1 ; A = aggregate(H) + b1
    k_gemm<<<gGemm, 256>>>(x, W1, H);
    k_aggregate<<<gAgg, TB>>>(H, b1, A);

    // bn + relu  -> P (stored in H)
    k_zero_stats<<<1, CC>>>();
    k_stats<<<gStat, CC>>>(A);
    k_params<<<1, CC>>>(gamma2, beta2);
    k_bnrelu<<<gVec, TB>>>(A, H);

    // conv2: A = P @ W2 ; Z = aggregate(A) + b2  -> d_out
    k_gemm<<<gGemm, 256>>>(H, W2, A);
    k_aggregate<<<gAgg, TB>>>(A, b2, out);

    // bn + residual + relu (in place on d_out)
    k_zero_stats<<<1, CC>>>();
    k_stats<<<gStat, CC>>>(out);
    k_params<<<1, CC>>>(gamma2, beta2);
    k_final<<<gVec, TB>>>(out, x, out);
}

// round 11
// speedup vs baseline: 1.0023x; 1.0023x over previous
#include <cuda_runtime.h>

// Problem constants (fixed shapes)
#define NN 100000
#define EE 1600000
#define CC 128
#define BN_EPS 1e-5f

// ---------------- scratch (device globals: no allocation allowed) ----------
__device__ int   g_is64;                 // edge_index dtype flag (1 = int64)
__device__ int   g_count[NN];
__device__ int   g_offsets[NN + 1];
__device__ int   g_cursor[NN];
__device__ int   g_csr[EE];
__device__ float g_dinv[NN];
__device__ float g_H[(size_t)NN * CC];   // 51.2 MB
__device__ float g_A[(size_t)NN * CC];   // 51.2 MB
__device__ int   g_bsum[128];            // scan block partials (98 used)
__device__ float g_sum[CC];
__device__ float g_sumsq[CC];
__device__ float g_scale[CC];
__device__ float g_shift[CC];

// ---------------- edge dtype detection --------------------------------------
// int64 node ids (< 2^31, non-negative) have all-zero high 32-bit words.
__global__ void k_detect(const unsigned int* __restrict__ w) {
    int nz = 0;
    for (int i = threadIdx.x; i < 512; i += 32)
        if (w[2 * i + 1] != 0u) nz++;
#pragma unroll
    for (int o = 16; o; o >>= 1) nz += __shfl_xor_sync(0xffffffffu, nz, o);
    if (threadIdx.x == 0) g_is64 = (nz == 0) ? 1 : 0;
}

__device__ __forceinline__ int edge_at(const void* eiv, int idx) {
    if (g_is64) return (int)((const long long*)eiv)[idx];
    return ((const int*)eiv)[idx];
}

// ---------------- CSR build --------------------------------------------------
__global__ void k_zero_count() {
    int i = blockIdx.x * blockDim.x + threadIdx.x;
    if (i < NN) g_count[i] = 0;
}

__global__ void k_hist(const void* __restrict__ eiv) {
    int e = blockIdx.x * blockDim.x + threadIdx.x;
    if (e < EE) atomicAdd(&g_count[edge_at(eiv, EE + e)], 1);
}

// 98 blocks x 256 threads, segment = 1024 counts per block
__global__ void k_scan_partial() {
    __shared__ int s[256];
    int b = blockIdx.x, t = threadIdx.x;
    int sum = 0;
    for (int i = t; i < 1024; i += 256) {
        int idx = b * 1024 + i;
        if (idx < NN) sum += g_count[idx];
    }
    s[t] = sum;
    __syncthreads();
    for (int off = 128; off > 0; off >>= 1) {
        if (t < off) s[t] += s[t + off];
        __syncthreads();
    }
    if (t == 0) g_bsum[b] = s[0];
}

__global__ void k_scan_boff() {   // 1 block, 128 threads
    __shared__ int s[128];
    int t = threadIdx.x;
    s[t] = (t < 98) ? g_bsum[t] : 0;
    __syncthreads();
    if (t == 0) {
        int run = 0;
        for (int i = 0; i < 98; i++) { int v = s[i]; s[i] = run; run += v; }
    }
    __syncthreads();
    if (t < 98) g_bsum[t] = s[t];
}

// 98 blocks x 256 threads: write exclusive offsets, cursor, dinv
__global__ void k_scan_write() {
    __shared__ int s[256];
    int b = blockIdx.x, t = threadIdx.x;
    int run = g_bsum[b];
    for (int tile = 0; tile < 4; tile++) {
        int idx = b * 1024 + tile * 256 + t;
        int v = (idx < NN) ? g_count[idx] : 0;
        s[t] = v;
        __syncthreads();
        for (int off = 1; off < 256; off <<= 1) {
            int add = (t >= off) ? s[t - off] : 0;
            __syncthreads();
            s[t] += add;
            __syncthreads();
        }
        int excl = s[t] - v;
        if (idx <= NN) g_offsets[idx] = run + excl;
        if (idx < NN) {
            g_cursor[idx] = run + excl;
            g_dinv[idx]   = rsqrtf((float)v + 1.0f);
        }
        int tot = s[255];
        __syncthreads();
        run += tot;
    }
}

__global__ void k_fill(const void* __restrict__ eiv) {
    int e = blockIdx.x * blockDim.x + threadIdx.x;
    if (e < EE) {
        int dst = edge_at(eiv, EE + e);
        int src = edge_at(eiv, e);
        int pos = atomicAdd(&g_cursor[dst], 1);
        g_csr[pos] = src;
    }
}

// ---------------- GEMM: C[NN,128] = f(A)[NN,128] x W[128,128] (fp32) --------
// Tile 128x128, 256 threads, thread micro-tile 8 rows x (4+4) cols.
// A staged TRANSPOSED in smem (sAT[k][m]) so inner loop = 4x LDS.128 + 64 FFMA.
// use_bn: apply y = relu(a*scale[c] + shift[c]) on the A-tile load (fuses BN).
__global__ __launch_bounds__(256, 2) void k_gemm(const float* __restrict__ A,
                                                 const float* __restrict__ W,
                                                 float* __restrict__ Cout,
                                                 int use_bn) {
    __shared__ float sAT[32][132];   // [k][m] padded: 33-word row stride
    __shared__ float sB[32][128];
    __shared__ float s_sc[128], s_sh[128];
    int tid = threadIdx.x;
    int tx = tid & 15;               // cols tx*4..+3 and 64+tx*4..+3
    int ty = tid >> 4;               // rows ty*8..+7
    int row0 = blockIdx.x * 128;

    if (use_bn && tid < 128) { s_sc[tid] = g_scale[tid]; s_sh[tid] = g_shift[tid]; }

    float4 acc[8][2];
#pragma unroll
    for (int i = 0; i < 8; i++) {
        acc[i][0] = make_float4(0.f, 0.f, 0.f, 0.f);
        acc[i][1] = make_float4(0.f, 0.f, 0.f, 0.f);
    }

    for (int kc = 0; kc < CC; kc += 32) {
        __syncthreads();   // prior compute done (and s_sc ready on iter 0)
        // A tile: 128 rows x 32 k, transposed into sAT
#pragma unroll
        for (int u = 0; u < 4; u++) {
            int f = tid + u * 256;        // 0..1023
            int m = f >> 3;               // row within tile
            int kk = (f & 7) * 4;         // k within chunk
            int r = row0 + m;
            float4 v = make_float4(0.f, 0.f, 0.f, 0.f);
            if (r < NN) {
                v = *(const float4*)(A + (size_t)r * CC + kc + kk);
                if (use_bn) {
                    v.x = fmaxf(v.x * s_sc[kc + kk + 0] + s_sh[kc + kk + 0], 0.f);
                    v.y = fmaxf(v.y * s_sc[kc + kk + 1] + s_sh[kc + kk + 1], 0.f);
                    v.z = fmaxf(v.z * s_sc[kc + kk + 2] + s_sh[kc + kk + 2], 0.f);
                    v.w = fmaxf(v.w * s_sc[kc + kk + 3] + s_sh[kc + kk + 3], 0.f);
                }
            }
            sAT[kk + 0][m] = v.x;
            sAT[kk + 1][m] = v.y;
            sAT[kk + 2][m] = v.z;
            sAT[kk + 3][m] = v.w;
        }
        // W tile: 32 x 128
#pragma unroll
        for (int u = 0; u < 4; u++) {
            int f = tid + u * 256;
            int k = f >> 5;
            int n = (f & 31) * 4;
            *(float4*)(&sB[k][n]) = *(const float4*)(W + (size_t)(kc + k) * CC + n);
        }
        __syncthreads();
#pragma unroll
        for (int k = 0; k < 32; k++) {
            float4 a0 = *(const float4*)(&sAT[k][ty * 8]);
            float4 a1 = *(const float4*)(&sAT[k][ty * 8 + 4]);
            float4 b0 = *(const float4*)(&sB[k][tx * 4]);
            float4 b1 = *(const float4*)(&sB[k][64 + tx * 4]);
            float ar[8] = {a0.x, a0.y, a0.z, a0.w, a1.x, a1.y, a1.z, a1.w};
#pragma unroll
            for (int i = 0; i < 8; i++) {
                acc[i][0].x += ar[i] * b0.x;
                acc[i][0].y += ar[i] * b0.y;
                acc[i][0].z += ar[i] * b0.z;
                acc[i][0].w += ar[i] * b0.w;
                acc[i][1].x += ar[i] * b1.x;
                acc[i][1].y += ar[i] * b1.y;
                acc[i][1].z += ar[i] * b1.z;
                acc[i][1].w += ar[i] * b1.w;
            }
        }
    }
#pragma unroll
    for (int i = 0; i < 8; i++) {
        int r = row0 + ty * 8 + i;
        if (r < NN) {
            *(float4*)(Cout + (size_t)r * CC + tx * 4)      = acc[i][0];
            *(float4*)(Cout + (size_t)r * CC + 64 + tx * 4) = acc[i][1];
        }
    }
}

// ---------------- aggregation: one warp per dst node -------------------------
__global__ __launch_bounds__(256) void k_aggregate(const float* __restrict__ Hin,
                                                   const float* __restrict__ bias,
                                                   float* __restrict__ Aout) {
    int gw = (blockIdx.x * blockDim.x + threadIdx.x) >> 5;
    int lane = threadIdx.x & 31;
    if (gw >= NN) return;
    int i = gw;
    int beg = g_offsets[i], end = g_offsets[i + 1];
    float4 acc0 = make_float4(0.f, 0.f, 0.f, 0.f);
    float4 acc1 = make_float4(0.f, 0.f, 0.f, 0.f);
    int e = beg;
    for (; e + 1 < end; e += 2) {
        int s0 = g_csr[e];
        int s1 = g_csr[e + 1];
        float w0 = g_dinv[s0];
        float w1 = g_dinv[s1];
        float4 h0 = *(const float4*)(Hin + (size_t)s0 * CC + lane * 4);
        float4 h1 = *(const float4*)(Hin + (size_t)s1 * CC + lane * 4);
        acc0.x += h0.x * w0; acc0.y += h0.y * w0;
        acc0.z += h0.z * w0; acc0.w += h0.w * w0;
        acc1.x += h1.x * w1; acc1.y += h1.y * w1;
        acc1.z += h1.z * w1; acc1.w += h1.w * w1;
    }
    if (e < end) {
        int s0 = g_csr[e];
        float w0 = g_dinv[s0];
        float4 h0 = *(const float4*)(Hin + (size_t)s0 * CC + lane * 4);
        acc0.x += h0.x * w0; acc0.y += h0.y * w0;
        acc0.z += h0.z * w0; acc0.w += h0.w * w0;
    }
    acc0.x += acc1.x; acc0.y += acc1.y; acc0.z += acc1.z; acc0.w += acc1.w;

    float di = g_dinv[i];
    float dii = di * di;
    float4 hs = *(const float4*)(Hin + (size_t)i * CC + lane * 4);
    float4 bb = *(const float4*)(bias + lane * 4);
    float4 o;
    o.x = acc0.x * di + hs.x * dii + bb.x;
    o.y = acc0.y * di + hs.y * dii + bb.y;
    o.z = acc0.z * di + hs.z * dii + bb.z;
    o.w = acc0.w * di + hs.w * dii + bb.w;
    *(float4*)(Aout + (size_t)i * CC + lane * 4) = o;
}

// ---------------- BatchNorm --------------------------------------------------
__global__ void k_zero_stats() {
    int c = threadIdx.x;
    g_sum[c] = 0.f;
    g_sumsq[c] = 0.f;
}

// block = 128 threads (one per channel), 256 rows per block
__global__ __launch_bounds__(128) void k_stats(const float* __restrict__ X) {
    int c = threadIdx.x;
    int r0 = blockIdx.x * 256;
    float s = 0.f, sq = 0.f;
#pragma unroll 4
    for (int r = 0; r < 256; r++) {
        int row = r0 + r;
        if (row < NN) {
            float v = X[(size_t)row * CC + c];
            s += v;
            sq += v * v;
        }
    }
    atomicAdd(&g_sum[c], s);
    atomicAdd(&g_sumsq[c], sq);
}

__global__ void k_params(const float* __restrict__ gamma,
                         const float* __restrict__ beta) {
    int c = threadIdx.x;
    float inv_n = 1.0f / (float)NN;
    float mean = g_sum[c] * inv_n;
    float var = g_sumsq[c] * inv_n - mean * mean;
    float istd = rsqrtf(var + BN_EPS);
    float sc = istd * gamma[c];
    g_scale[c] = sc;
    g_shift[c] = beta[c] - mean * sc;
}

// relu(bn(z) + x) elementwise (final), in-place on d_out
__global__ __launch_bounds__(256) void k_final(const float* __restrict__ Z,
                                               const float* __restrict__ Xres,
                                               float* __restrict__ Out) {
    int idx = blockIdx.x * blockDim.x + threadIdx.x;
    if (idx >= NN * 32) return;
    int c = (idx & 31) * 4;
    float4 sc = *(const float4*)(&g_scale[c]);
    float4 sh = *(const float4*)(&g_shift[c]);
    float4 v = ((const float4*)Z)[idx];
    float4 xv = ((const float4*)Xres)[idx];
    v.x = fmaxf(v.x * sc.x + sh.x + xv.x, 0.f);
    v.y = fmaxf(v.y * sc.y + sh.y + xv.y, 0.f);
    v.z = fmaxf(v.z * sc.z + sh.z + xv.z, 0.f);
    v.w = fmaxf(v.w * sc.w + sh.w + xv.w, 0.f);
    ((float4*)Out)[idx] = v;
}

// ---------------- launch -----------------------------------------------------
extern "C" void kernel_launch(void* const* d_in, const int* in_sizes, int n_in,
                              void* d_out, int out_size) {
    (void)in_sizes; (void)n_in; (void)out_size;
    const float* x      = (const float*)d_in[0];
    const float* W1     = (const float*)d_in[1];
    const float* b1     = (const float*)d_in[2];
    const float* W2     = (const float*)d_in[3];
    const float* b2     = (const float*)d_in[4];
    const float* gamma2 = (const float*)d_in[5];
    const float* beta2  = (const float*)d_in[6];
    const void*  ei     = d_in[7];
    float* out = (float*)d_out;

    float* H = nullptr;
    float* A = nullptr;
    cudaGetSymbolAddress((void**)&H, g_H);
    cudaGetSymbolAddress((void**)&A, g_A);

    const int TB = 256;
    const int gN    = (NN + TB - 1) / TB;            // 391
    const int gE    = (EE + TB - 1) / TB;            // 6250
    const int gGemm = (NN + 127) / 128;              // 782
    const int gAgg  = (NN * 32 + TB - 1) / TB;       // 12500 (8 warps/block)
    const int gVec  = (NN * 32 + TB - 1) / TB;       // 12500
    const int gStat = (NN + 255) / 256;              // 391

    // edge dtype detect + CSR build (once per launch; used by both convs)
    k_detect<<<1, 32>>>((const unsigned int*)ei);
    k_zero_count<<<gN, TB>>>();
    k_hist<<<gE, TB>>>(ei);
    k_scan_partial<<<98, 256>>>();
    k_scan_boff<<<1, 128>>>();
    k_scan_write<<<98, 256>>>();
    k_fill<<<gE, TB>>>(ei);

    // conv1: H = x @ W1 ; A = aggregate(H) + b1
    k_gemm<<<gGemm, 256>>>(x, W1, H, 0);
    k_aggregate<<<gAgg, TB>>>(H, b1, A);

    // bn1 stats/params (bn+relu applied inside GEMM2's A load)
    k_zero_stats<<<1, CC>>>();
    k_stats<<<gStat, CC>>>(A);
    k_params<<<1, CC>>>(gamma2, beta2);

    // conv2: H = relu(bn(A)) @ W2 ; Z = aggregate(H) + b2 -> d_out
    k_gemm<<<gGemm, 256>>>(A, W2, H, 1);
    k_aggregate<<<gAgg, TB>>>(H, b2, out);

    // bn2 + residual + relu (in place on d_out)
    k_zero_stats<<<1, CC>>>();
    k_stats<<<gStat, CC>>>(out);
    k_params<<<1, CC>>>(gamma2, beta2);
    k_final<<<gVec, TB>>>(out, x, out);
}